// round 5
// baseline (speedup 1.0000x reference)
#include <cuda_runtime.h>

#define BQ 64
#define TQ 2048
#define HD 128
#define M_TOTAL (BQ * TQ)

// Scratch for x_proj, padded by 2 timesteps so the recurrence prefetch can be
// unconditional (allocation-free rule: __device__ global array).
__device__ float g_xproj[(size_t)M_TOTAL * HD + 2 * HD];

// ---- packed fp32x2 helpers (sm_100+) ---------------------------------------
__device__ __forceinline__ void ffma2(unsigned long long& d,
                                      unsigned long long a,
                                      unsigned long long b) {
    asm("fma.rn.f32x2 %0, %1, %2, %0;" : "+l"(d) : "l"(a), "l"(b));
}
__device__ __forceinline__ unsigned long long addf2(unsigned long long a,
                                                    unsigned long long b) {
    unsigned long long d;
    asm("add.rn.f32x2 %0, %1, %2;" : "=l"(d) : "l"(a), "l"(b));
    return d;
}
__device__ __forceinline__ unsigned long long pack2(float lo, float hi) {
    unsigned long long p;
    asm("mov.b64 %0, {%1, %2};" : "=l"(p) : "r"(__float_as_uint(lo)), "r"(__float_as_uint(hi)));
    return p;
}
__device__ __forceinline__ void unpack2(unsigned long long p, float& lo, float& hi) {
    unsigned int a, b;
    asm("mov.b64 {%0, %1}, %2;" : "=r"(a), "=r"(b) : "l"(p));
    lo = __uint_as_float(a);
    hi = __uint_as_float(b);
}

// ---------------------------------------------------------------------------
// GEMM: C[m][n] = sum_k A[m][k] * W[n][k] + bias[n] (+ bias2[n])
// 64 rows/CTA, N=K=128. 128 threads, 8m x 8n register tile, FFMA2.
// Thread's n-columns are {tx*4..+3} and {64+tx*4..+3} so every Wt LDS.128
// phase-group reads a contiguous 128B span -> bank-conflict-free.
// ---------------------------------------------------------------------------
__global__ __launch_bounds__(128, 3) void gemm128_kernel(
    const float* __restrict__ A, const float* __restrict__ W,
    const float* __restrict__ bias, const float* __restrict__ bias2,
    float* __restrict__ C)
{
    __shared__ __align__(16) float Wt[64 * 128];  // [k][n]  (32KB)
    __shared__ __align__(16) float At[64 * 64];   // [k][m]  (16KB)

    const int tid = threadIdx.x;
    const int m0 = blockIdx.x * 64;
    const int tx = tid & 15;   // n: cols tx*4..+3 and 64+tx*4..+3
    const int ty = tid >> 4;   // m: rows ty*8..+7   (ty in 0..7)

    unsigned long long acc2[8][4];
#pragma unroll
    for (int i = 0; i < 8; i++)
#pragma unroll
        for (int j = 0; j < 4; j++) acc2[i][j] = 0ull;

#pragma unroll
    for (int kc = 0; kc < 2; kc++) {
        // W staging: lanes cover consecutive n -> STS bank-conflict-free.
        for (int i = tid; i < 128 * 16; i += 128) {
            int n  = i & 127;
            int k0 = (i >> 7) << 2;
            float4 v = *(const float4*)(W + (size_t)n * 128 + kc * 64 + k0);
            Wt[(k0 + 0) * 128 + n] = v.x;
            Wt[(k0 + 1) * 128 + n] = v.y;
            Wt[(k0 + 2) * 128 + n] = v.z;
            Wt[(k0 + 3) * 128 + n] = v.w;
        }
        // A staging: lanes cover consecutive m -> STS bank-conflict-free.
        for (int i = tid; i < 64 * 16; i += 128) {
            int m  = i & 63;
            int k0 = (i >> 6) << 2;
            float4 v = *(const float4*)(A + (size_t)(m0 + m) * 128 + kc * 64 + k0);
            At[(k0 + 0) * 64 + m] = v.x;
            At[(k0 + 1) * 64 + m] = v.y;
            At[(k0 + 2) * 64 + m] = v.z;
            At[(k0 + 3) * 64 + m] = v.w;
        }
        __syncthreads();

#pragma unroll 8
        for (int k = 0; k < 64; k++) {
            float4 a0 = *(const float4*)(At + k * 64 + ty * 8);
            float4 a1 = *(const float4*)(At + k * 64 + ty * 8 + 4);
            ulonglong2 w0 = *(const ulonglong2*)(Wt + k * 128 + tx * 4);       // n = tx*4..+3
            ulonglong2 w1 = *(const ulonglong2*)(Wt + k * 128 + 64 + tx * 4);  // n = 64+tx*4..+3
            float am[8] = {a0.x, a0.y, a0.z, a0.w, a1.x, a1.y, a1.z, a1.w};
#pragma unroll
            for (int i = 0; i < 8; i++) {
                unsigned long long ad = pack2(am[i], am[i]);
                ffma2(acc2[i][0], ad, w0.x);
                ffma2(acc2[i][1], ad, w0.y);
                ffma2(acc2[i][2], ad, w1.x);
                ffma2(acc2[i][3], ad, w1.y);
            }
        }
        __syncthreads();
    }

    // epilogue: bias for the 8 owned columns
    float bb[8];
#pragma unroll
    for (int j = 0; j < 4; j++) {
        bb[j]     = bias[tx * 4 + j];
        bb[4 + j] = bias[64 + tx * 4 + j];
        if (bias2) {
            bb[j]     += bias2[tx * 4 + j];
            bb[4 + j] += bias2[64 + tx * 4 + j];
        }
    }
#pragma unroll
    for (int i = 0; i < 8; i++) {
        const int m = m0 + ty * 8 + i;
        float c[8];
#pragma unroll
        for (int j = 0; j < 4; j++) unpack2(acc2[i][j], c[2 * j], c[2 * j + 1]);
#pragma unroll
        for (int j = 0; j < 8; j++) c[j] += bb[j];
        float* crow = C + (size_t)m * 128;
        *(float4*)(crow + tx * 4)      = make_float4(c[0], c[1], c[2], c[3]);
        *(float4*)(crow + 64 + tx * 4) = make_float4(c[4], c[5], c[6], c[7]);
    }
}

// ---------------------------------------------------------------------------
// Recurrence: one CTA per batch row. 256 threads: j = tid>>1, half = tid&1.
// 64-wide partial dot with FFMA2 (4 accs), packed-add reduce tree, pair
// reduction via shfl_xor. Double-buffered h -> ONE barrier/step. t-loop
// unrolled x2 to constant-fold buffer indices. Unconditional prefetch
// (xproj padded). Fast tanh = 1 - 2/(e^{2x}+1).
// ---------------------------------------------------------------------------
__global__ __launch_bounds__(256, 1) void rnn_rec_kernel(
    const float* __restrict__ xproj, const float* __restrict__ Whh,
    float* __restrict__ hidden)
{
    __shared__ __align__(16) float sh_h[2][HD];

    const int tid  = threadIdx.x;
    const int j    = tid >> 1;
    const int half = tid & 1;
    const int b    = blockIdx.x;

    // my 64 weights W_hh[j][half*64 + k], packed as 32 fp32x2 pairs
    unsigned long long w2[32];
    {
        const ulonglong2* wp = (const ulonglong2*)(Whh + (size_t)j * 128 + half * 64);
#pragma unroll
        for (int i = 0; i < 16; i++) {
            ulonglong2 v = wp[i];
            w2[2 * i]     = v.x;
            w2[2 * i + 1] = v.y;
        }
    }

    if (tid < HD) sh_h[0][tid] = 0.f;

    const float* xp   = xproj + (size_t)b * TQ * HD + j;
    float*       hout = hidden + (size_t)b * TQ * HD + j;

    float xp0 = xp[0];
    float xp1 = xp[HD];
    __syncthreads();

    const ulonglong2* hp0 = (const ulonglong2*)(&sh_h[0][half * 64]);
    const ulonglong2* hp1 = (const ulonglong2*)(&sh_h[1][half * 64]);

#pragma unroll 1
    for (int t = 0; t < TQ; t += 2) {
#pragma unroll
        for (int u = 0; u < 2; u++) {
            const ulonglong2* hp = u ? hp1 : hp0;
            float* shw = u ? sh_h[0] : sh_h[1];

            float xpn = __ldg(xp + (size_t)(t + u + 2) * HD);  // padded: safe

            unsigned long long a2[4] = {0ull, 0ull, 0ull, 0ull};
#pragma unroll
            for (int i = 0; i < 16; i++) {
                ulonglong2 hv = hp[i];
                ffma2(a2[i & 3], hv.x, w2[2 * i]);
                ffma2(a2[i & 3], hv.y, w2[2 * i + 1]);
            }
            // packed reduce tree: 4 accs -> 1 packed -> scalar
            unsigned long long p = addf2(addf2(a2[0], a2[1]), addf2(a2[2], a2[3]));
            float lo, hi;
            unpack2(p, lo, hi);
            float s = lo + hi;
            s += __shfl_xor_sync(0xffffffffu, s, 1);  // pair halves

            const float x = s + xp0;
            // tanh(x) = 1 - 2/(exp(2x)+1)   (~1e-6 rel err)
            const float e  = __expf(2.f * x);
            const float hn = 1.f - __fdividef(2.f, e + 1.f);

            // split the two stores across the pair lanes
            if (half) shw[j] = hn;
            else      hout[(size_t)(t + u) * HD] = hn;

            xp0 = xp1;
            xp1 = xpn;
            __syncthreads();
        }
    }
}

// ---------------------------------------------------------------------------
extern "C" void kernel_launch(void* const* d_in, const int* in_sizes, int n_in,
                              void* d_out, int out_size)
{
    const float* seq  = (const float*)d_in[0];
    const float* Wih  = (const float*)d_in[1];
    const float* bih  = (const float*)d_in[2];
    const float* Whh  = (const float*)d_in[3];
    const float* bhh  = (const float*)d_in[4];
    const float* Wout = (const float*)d_in[5];
    const float* bout = (const float*)d_in[6];

    float* hid = (float*)d_out;                  // hidden_states (B,T,H)
    float* out = hid + (size_t)M_TOTAL * HD;     // output_states (B,T,H)

    float* xproj;
    cudaGetSymbolAddress((void**)&xproj, g_xproj);

    gemm128_kernel<<<M_TOTAL / 64, 128>>>(seq, Wih, bih, bhh, xproj);
    rnn_rec_kernel<<<BQ, 256>>>(xproj, Whh, hid);
    gemm128_kernel<<<M_TOTAL / 64, 128>>>(hid, Wout, bout, nullptr, out);
}

// round 6
// speedup vs baseline: 1.4251x; 1.4251x over previous
#include <cuda_runtime.h>

#define BQ 64
#define TQ 2048
#define HD 128
#define M_TOTAL (BQ * TQ)
#define CHUNK 8   // xp rows staged per cp.async group

// Scratch for x_proj, padded by 2 chunks so the cp.async prefetch can run
// unconditionally past the end (allocation-free rule: __device__ global array).
__device__ float g_xproj[(size_t)M_TOTAL * HD + 2 * CHUNK * HD];

// ---- packed fp32x2 helpers (sm_100+) ---------------------------------------
__device__ __forceinline__ void ffma2(unsigned long long& d,
                                      unsigned long long a,
                                      unsigned long long b) {
    asm("fma.rn.f32x2 %0, %1, %2, %0;" : "+l"(d) : "l"(a), "l"(b));
}
__device__ __forceinline__ unsigned long long pack2(float lo, float hi) {
    unsigned long long p;
    asm("mov.b64 %0, {%1, %2};" : "=l"(p) : "r"(__float_as_uint(lo)), "r"(__float_as_uint(hi)));
    return p;
}
__device__ __forceinline__ void unpack2(unsigned long long p, float& lo, float& hi) {
    unsigned int a, b;
    asm("mov.b64 {%0, %1}, %2;" : "=r"(a), "=r"(b) : "l"(p));
    lo = __uint_as_float(a);
    hi = __uint_as_float(b);
}
__device__ __forceinline__ unsigned int smem_u32(const void* p) {
    unsigned int a;
    asm("{ .reg .u64 t; cvta.to.shared.u64 t, %1; cvt.u32.u64 %0, t; }" : "=r"(a) : "l"(p));
    return a;
}
__device__ __forceinline__ void cp_async16(unsigned int dst, const void* src) {
    asm volatile("cp.async.cg.shared.global [%0], [%1], 16;" :: "r"(dst), "l"(src));
}
__device__ __forceinline__ void cp_commit() {
    asm volatile("cp.async.commit_group;");
}
template <int N> __device__ __forceinline__ void cp_wait() {
    asm volatile("cp.async.wait_group %0;" :: "n"(N));
}

// ---------------------------------------------------------------------------
// GEMM: C[m][n] = sum_k A[m][k] * W[n][k] + bias[n] (+ bias2[n])
// 64 rows/CTA, N=K=128. 128 threads, 8m x 8n register tile, FFMA2.
// (unchanged from R5: measured 120.8us)
// ---------------------------------------------------------------------------
__global__ __launch_bounds__(128, 3) void gemm128_kernel(
    const float* __restrict__ A, const float* __restrict__ W,
    const float* __restrict__ bias, const float* __restrict__ bias2,
    float* __restrict__ C)
{
    __shared__ __align__(16) float Wt[64 * 128];  // [k][n]  (32KB)
    __shared__ __align__(16) float At[64 * 64];   // [k][m]  (16KB)

    const int tid = threadIdx.x;
    const int m0 = blockIdx.x * 64;
    const int tx = tid & 15;   // n: cols tx*4..+3 and 64+tx*4..+3
    const int ty = tid >> 4;   // m: rows ty*8..+7

    unsigned long long acc2[8][4];
#pragma unroll
    for (int i = 0; i < 8; i++)
#pragma unroll
        for (int j = 0; j < 4; j++) acc2[i][j] = 0ull;

#pragma unroll
    for (int kc = 0; kc < 2; kc++) {
        for (int i = tid; i < 128 * 16; i += 128) {
            int n  = i & 127;
            int k0 = (i >> 7) << 2;
            float4 v = *(const float4*)(W + (size_t)n * 128 + kc * 64 + k0);
            Wt[(k0 + 0) * 128 + n] = v.x;
            Wt[(k0 + 1) * 128 + n] = v.y;
            Wt[(k0 + 2) * 128 + n] = v.z;
            Wt[(k0 + 3) * 128 + n] = v.w;
        }
        for (int i = tid; i < 64 * 16; i += 128) {
            int m  = i & 63;
            int k0 = (i >> 6) << 2;
            float4 v = *(const float4*)(A + (size_t)(m0 + m) * 128 + kc * 64 + k0);
            At[(k0 + 0) * 64 + m] = v.x;
            At[(k0 + 1) * 64 + m] = v.y;
            At[(k0 + 2) * 64 + m] = v.z;
            At[(k0 + 3) * 64 + m] = v.w;
        }
        __syncthreads();

#pragma unroll 8
        for (int k = 0; k < 64; k++) {
            float4 a0 = *(const float4*)(At + k * 64 + ty * 8);
            float4 a1 = *(const float4*)(At + k * 64 + ty * 8 + 4);
            ulonglong2 w0 = *(const ulonglong2*)(Wt + k * 128 + tx * 4);
            ulonglong2 w1 = *(const ulonglong2*)(Wt + k * 128 + 64 + tx * 4);
            float am[8] = {a0.x, a0.y, a0.z, a0.w, a1.x, a1.y, a1.z, a1.w};
#pragma unroll
            for (int i = 0; i < 8; i++) {
                unsigned long long ad = pack2(am[i], am[i]);
                ffma2(acc2[i][0], ad, w0.x);
                ffma2(acc2[i][1], ad, w0.y);
                ffma2(acc2[i][2], ad, w1.x);
                ffma2(acc2[i][3], ad, w1.y);
            }
        }
        __syncthreads();
    }

    float bb[8];
#pragma unroll
    for (int j = 0; j < 4; j++) {
        bb[j]     = bias[tx * 4 + j];
        bb[4 + j] = bias[64 + tx * 4 + j];
        if (bias2) {
            bb[j]     += bias2[tx * 4 + j];
            bb[4 + j] += bias2[64 + tx * 4 + j];
        }
    }
#pragma unroll
    for (int i = 0; i < 8; i++) {
        const int m = m0 + ty * 8 + i;
        float c[8];
#pragma unroll
        for (int j = 0; j < 4; j++) unpack2(acc2[i][j], c[2 * j], c[2 * j + 1]);
#pragma unroll
        for (int j = 0; j < 8; j++) c[j] += bb[j];
        float* crow = C + (size_t)m * 128;
        *(float4*)(crow + tx * 4)      = make_float4(c[0], c[1], c[2], c[3]);
        *(float4*)(crow + 64 + tx * 4) = make_float4(c[4], c[5], c[6], c[7]);
    }
}

// ---------------------------------------------------------------------------
// Recurrence: one CTA per batch row. 256 threads: j = tid>>1, half = tid&1.
// R4 structure (known-good), ONE change: xp staged into SMEM via cp.async
// in 8-row chunks, double-buffered, lead = 8-16 steps. The per-step xp read
// is a 29-cyc LDS instead of a lead-2 DRAM load.
// ---------------------------------------------------------------------------
__global__ __launch_bounds__(256, 1) void rnn_rec_kernel(
    const float* __restrict__ xproj, const float* __restrict__ Whh,
    float* __restrict__ hidden)
{
    __shared__ __align__(16) float sh_h[2][HD];
    __shared__ __align__(16) float sh_xp[2][CHUNK][HD];

    const int tid  = threadIdx.x;
    const int j    = tid >> 1;
    const int half = tid & 1;
    const int b    = blockIdx.x;

    // my 64 weights W_hh[j][half*64 + k], packed as 32 fp32x2 pairs
    unsigned long long w2[32];
    {
        const ulonglong2* wp = (const ulonglong2*)(Whh + (size_t)j * 128 + half * 64);
#pragma unroll
        for (int i = 0; i < 16; i++) {
            ulonglong2 v = wp[i];
            w2[2 * i]     = v.x;
            w2[2 * i + 1] = v.y;
        }
    }

    if (tid < HD) sh_h[0][tid] = 0.f;

    const float* xp   = xproj + (size_t)b * TQ * HD;
    float*       hout = hidden + (size_t)b * TQ * HD + j;

    // cp.async staging geometry: each thread copies 16B of the 4KB chunk
    const int cp_row = (tid * 4) >> 7;   // 0..7
    const int cp_col = (tid * 4) & 127;
    const unsigned int dst0 = smem_u32(&sh_xp[0][cp_row][cp_col]);
    const unsigned int dst1 = smem_u32(&sh_xp[1][cp_row][cp_col]);
    const float* src_base = xp + (size_t)cp_row * HD + cp_col;

    // preload chunks 0 and 1
    cp_async16(dst0, src_base);
    cp_commit();
    cp_async16(dst1, src_base + CHUNK * HD);
    cp_commit();

    __syncthreads();  // sh_h init visible

#pragma unroll 1
    for (int tc = 0; tc < TQ / CHUNK; tc++) {
        cp_wait<1>();     // chunk tc landed (chunk tc+1 may be in flight)
        __syncthreads();  // make it visible to all threads

        const float* xrow = &sh_xp[tc & 1][0][j];

#pragma unroll
        for (int u = 0; u < CHUNK; u++) {
            // t = tc*CHUNK + u ; parity = u&1 since CHUNK is even
            const ulonglong2* hp = (const ulonglong2*)(&sh_h[u & 1][half * 64]);

            unsigned long long a2[4] = {0ull, 0ull, 0ull, 0ull};
#pragma unroll
            for (int i = 0; i < 16; i++) {
                ulonglong2 hv = hp[i];
                ffma2(a2[i & 3], hv.x, w2[2 * i]);
                ffma2(a2[i & 3], hv.y, w2[2 * i + 1]);
            }
            float s = 0.f;
#pragma unroll
            for (int i = 0; i < 4; i++) {
                float lo, hi;
                unpack2(a2[i], lo, hi);
                s += lo + hi;
            }
            s += __shfl_xor_sync(0xffffffffu, s, 1);  // pair halves

            const float x = s + xrow[(size_t)u * HD];
            // tanh(x) = 1 - 2/(exp(2x)+1)   (~1e-6 rel err)
            const float e  = __expf(2.f * x);
            const float hn = 1.f - __fdividef(2.f, e + 1.f);

            if (!half) {
                sh_h[(u + 1) & 1][j] = hn;
                hout[(size_t)(tc * CHUNK + u) * HD] = hn;
            }
            __syncthreads();
        }

        // all threads past the chunk's last consume -> safe to refill buffer
        cp_async16(tc & 1 ? dst1 : dst0, src_base + (size_t)(tc + 2) * CHUNK * HD);
        cp_commit();
    }
}

// ---------------------------------------------------------------------------
extern "C" void kernel_launch(void* const* d_in, const int* in_sizes, int n_in,
                              void* d_out, int out_size)
{
    const float* seq  = (const float*)d_in[0];
    const float* Wih  = (const float*)d_in[1];
    const float* bih  = (const float*)d_in[2];
    const float* Whh  = (const float*)d_in[3];
    const float* bhh  = (const float*)d_in[4];
    const float* Wout = (const float*)d_in[5];
    const float* bout = (const float*)d_in[6];

    float* hid = (float*)d_out;                  // hidden_states (B,T,H)
    float* out = hid + (size_t)M_TOTAL * HD;     // output_states (B,T,H)

    float* xproj;
    cudaGetSymbolAddress((void**)&xproj, g_xproj);

    gemm128_kernel<<<M_TOTAL / 64, 128>>>(seq, Wih, bih, bhh, xproj);
    rnn_rec_kernel<<<BQ, 256>>>(xproj, Whh, hid);
    gemm128_kernel<<<M_TOTAL / 64, 128>>>(hid, Wout, bout, nullptr, out);
}

// round 9
// speedup vs baseline: 2.0161x; 1.4147x over previous
#include <cuda_runtime.h>

#define BQ 64
#define TQ 2048
#define HD 128
#define M_TOTAL (BQ * TQ)
#define CHUNK 8   // xp rows staged per cp.async group

// Scratch for x_proj, padded by 2 chunks so the cp.async prefetch can run
// unconditionally past the end (allocation-free rule: __device__ global array).
__device__ float g_xproj[(size_t)M_TOTAL * HD + 2 * CHUNK * HD];

// ---- packed fp32x2 helpers (sm_100+) ---------------------------------------
__device__ __forceinline__ void ffma2(unsigned long long& d,
                                      unsigned long long a,
                                      unsigned long long b) {
    asm("fma.rn.f32x2 %0, %1, %2, %0;" : "+l"(d) : "l"(a), "l"(b));
}
__device__ __forceinline__ unsigned long long addf2(unsigned long long a,
                                                    unsigned long long b) {
    unsigned long long d;
    asm("add.rn.f32x2 %0, %1, %2;" : "=l"(d) : "l"(a), "l"(b));
    return d;
}
__device__ __forceinline__ unsigned long long pack2(float lo, float hi) {
    unsigned long long p;
    asm("mov.b64 %0, {%1, %2};" : "=l"(p) : "r"(__float_as_uint(lo)), "r"(__float_as_uint(hi)));
    return p;
}
__device__ __forceinline__ void unpack2(unsigned long long p, float& lo, float& hi) {
    unsigned int a, b;
    asm("mov.b64 {%0, %1}, %2;" : "=r"(a), "=r"(b) : "l"(p));
    lo = __uint_as_float(a);
    hi = __uint_as_float(b);
}
__device__ __forceinline__ unsigned int smem_u32(const void* p) {
    unsigned int a;
    asm("{ .reg .u64 t; cvta.to.shared.u64 t, %1; cvt.u32.u64 %0, t; }" : "=r"(a) : "l"(p));
    return a;
}
__device__ __forceinline__ void cp_async16(unsigned int dst, const void* src) {
    asm volatile("cp.async.cg.shared.global [%0], [%1], 16;" :: "r"(dst), "l"(src));
}
__device__ __forceinline__ void cp_commit() {
    asm volatile("cp.async.commit_group;");
}
template <int N> __device__ __forceinline__ void cp_wait() {
    asm volatile("cp.async.wait_group %0;" :: "n"(N));
}

// ---------------------------------------------------------------------------
// GEMM: C[m][n] = sum_k A[m][k] * W[n][k] + bias[n] (+ bias2[n])
// 64 rows/CTA, N=K=128. 128 threads, 8m x 8n register tile, FFMA2.
// (unchanged: measured ~121-126us)
// ---------------------------------------------------------------------------
__global__ __launch_bounds__(128, 3) void gemm128_kernel(
    const float* __restrict__ A, const float* __restrict__ W,
    const float* __restrict__ bias, const float* __restrict__ bias2,
    float* __restrict__ C)
{
    __shared__ __align__(16) float Wt[64 * 128];  // [k][n]  (32KB)
    __shared__ __align__(16) float At[64 * 64];   // [k][m]  (16KB)

    const int tid = threadIdx.x;
    const int m0 = blockIdx.x * 64;
    const int tx = tid & 15;
    const int ty = tid >> 4;

    unsigned long long acc2[8][4];
#pragma unroll
    for (int i = 0; i < 8; i++)
#pragma unroll
        for (int j = 0; j < 4; j++) acc2[i][j] = 0ull;

#pragma unroll
    for (int kc = 0; kc < 2; kc++) {
        for (int i = tid; i < 128 * 16; i += 128) {
            int n  = i & 127;
            int k0 = (i >> 7) << 2;
            float4 v = *(const float4*)(W + (size_t)n * 128 + kc * 64 + k0);
            Wt[(k0 + 0) * 128 + n] = v.x;
            Wt[(k0 + 1) * 128 + n] = v.y;
            Wt[(k0 + 2) * 128 + n] = v.z;
            Wt[(k0 + 3) * 128 + n] = v.w;
        }
        for (int i = tid; i < 64 * 16; i += 128) {
            int m  = i & 63;
            int k0 = (i >> 6) << 2;
            float4 v = *(const float4*)(A + (size_t)(m0 + m) * 128 + kc * 64 + k0);
            At[(k0 + 0) * 64 + m] = v.x;
            At[(k0 + 1) * 64 + m] = v.y;
            At[(k0 + 2) * 64 + m] = v.z;
            At[(k0 + 3) * 64 + m] = v.w;
        }
        __syncthreads();

#pragma unroll 8
        for (int k = 0; k < 64; k++) {
            float4 a0 = *(const float4*)(At + k * 64 + ty * 8);
            float4 a1 = *(const float4*)(At + k * 64 + ty * 8 + 4);
            ulonglong2 w0 = *(const ulonglong2*)(Wt + k * 128 + tx * 4);
            ulonglong2 w1 = *(const ulonglong2*)(Wt + k * 128 + 64 + tx * 4);
            float am[8] = {a0.x, a0.y, a0.z, a0.w, a1.x, a1.y, a1.z, a1.w};
#pragma unroll
            for (int i = 0; i < 8; i++) {
                unsigned long long ad = pack2(am[i], am[i]);
                ffma2(acc2[i][0], ad, w0.x);
                ffma2(acc2[i][1], ad, w0.y);
                ffma2(acc2[i][2], ad, w1.x);
                ffma2(acc2[i][3], ad, w1.y);
            }
        }
        __syncthreads();
    }

    float bb[8];
#pragma unroll
    for (int j = 0; j < 4; j++) {
        bb[j]     = bias[tx * 4 + j];
        bb[4 + j] = bias[64 + tx * 4 + j];
        if (bias2) {
            bb[j]     += bias2[tx * 4 + j];
            bb[4 + j] += bias2[64 + tx * 4 + j];
        }
    }
#pragma unroll
    for (int i = 0; i < 8; i++) {
        const int m = m0 + ty * 8 + i;
        float c[8];
#pragma unroll
        for (int j = 0; j < 4; j++) unpack2(acc2[i][j], c[2 * j], c[2 * j + 1]);
#pragma unroll
        for (int j = 0; j < 8; j++) c[j] += bb[j];
        float* crow = C + (size_t)m * 128;
        *(float4*)(crow + tx * 4)      = make_float4(c[0], c[1], c[2], c[3]);
        *(float4*)(crow + 64 + tx * 4) = make_float4(c[4], c[5], c[6], c[7]);
    }
}

// ---------------------------------------------------------------------------
// Recurrence: one CTA per batch row. 128 threads (4 warps, 1/SMSP).
// Thread j computes h[j] as a FULL 128-wide dot: W_hh row j entirely in
// registers (64 fp32x2), h read as pure broadcast LDS. No shfl reduce, no
// divergent stores. Double-buffered h -> ONE barrier/step. xp staged via
// cp.async (8-row chunks, double-buffered). Fast tanh = 1 - 2/(e^{2x}+1).
// ---------------------------------------------------------------------------
__global__ __launch_bounds__(128, 1) void rnn_rec_kernel(
    const float* __restrict__ xproj, const float* __restrict__ Whh,
    float* __restrict__ hidden)
{
    __shared__ __align__(16) float sh_h[2][HD];
    __shared__ __align__(16) float sh_xp[2][CHUNK][HD];

    const int tid = threadIdx.x;   // == j
    const int b   = blockIdx.x;

    // full W_hh row j in registers: 64 packed fp32x2
    unsigned long long w2[64];
    {
        const ulonglong2* wp = (const ulonglong2*)(Whh + (size_t)tid * 128);
#pragma unroll
        for (int i = 0; i < 32; i++) {
            ulonglong2 v = wp[i];
            w2[2 * i]     = v.x;
            w2[2 * i + 1] = v.y;
        }
    }

    sh_h[0][tid] = 0.f;

    const float* xp   = xproj + (size_t)b * TQ * HD;
    float*       hout = hidden + (size_t)b * TQ * HD + tid;

    // cp.async staging: 4KB chunk / 128 threads = 32B (2x16B) per thread
    const int cp_row = tid >> 4;          // 0..7
    const int cp_col = (tid & 15) * 8;    // 0..120 step 8
    const unsigned int dst0 = smem_u32(&sh_xp[0][cp_row][cp_col]);
    const unsigned int dst1 = smem_u32(&sh_xp[1][cp_row][cp_col]);
    const float* src_base = xp + (size_t)cp_row * HD + cp_col;

    cp_async16(dst0,      src_base);
    cp_async16(dst0 + 16, src_base + 4);
    cp_commit();
    cp_async16(dst1,      src_base + CHUNK * HD);
    cp_async16(dst1 + 16, src_base + CHUNK * HD + 4);
    cp_commit();

    __syncthreads();  // sh_h init visible

#pragma unroll 1
    for (int tc = 0; tc < TQ / CHUNK; tc++) {
        cp_wait<1>();     // chunk tc landed
        __syncthreads();

        const float* xrow = &sh_xp[tc & 1][0][tid];

#pragma unroll 2
        for (int u = 0; u < CHUNK; u++) {
            const ulonglong2* hp = (const ulonglong2*)(sh_h[u & 1]);

            unsigned long long a2[4] = {0ull, 0ull, 0ull, 0ull};
#pragma unroll
            for (int i = 0; i < 32; i++) {
                ulonglong2 hv = hp[i];           // broadcast: all lanes same addr
                ffma2(a2[i & 3], hv.x, w2[2 * i]);
                ffma2(a2[i & 3], hv.y, w2[2 * i + 1]);
            }
            unsigned long long p = addf2(addf2(a2[0], a2[1]), addf2(a2[2], a2[3]));
            float lo, hi;
            unpack2(p, lo, hi);

            const float x = lo + hi + xrow[(size_t)u * HD];
            // tanh(x) = 1 - 2/(exp(2x)+1)   (~1e-6 rel err)
            const float e  = __expf(2.f * x);
            const float hn = 1.f - __fdividef(2.f, e + 1.f);

            sh_h[(u + 1) & 1][tid] = hn;             // every thread: own j
            hout[(size_t)(tc * CHUNK + u) * HD] = hn;
            __syncthreads();
        }

        // refill the just-consumed buffer with chunk tc+2 (xproj padded)
        {
            const unsigned int d = (tc & 1) ? dst1 : dst0;
            const float* s = src_base + (size_t)(tc + 2) * CHUNK * HD;
            cp_async16(d,      s);
            cp_async16(d + 16, s + 4);
            cp_commit();
        }
    }
}

// ---------------------------------------------------------------------------
extern "C" void kernel_launch(void* const* d_in, const int* in_sizes, int n_in,
                              void* d_out, int out_size)
{
    const float* seq  = (const float*)d_in[0];
    const float* Wih  = (const float*)d_in[1];
    const float* bih  = (const float*)d_in[2];
    const float* Whh  = (const float*)d_in[3];
    const float* bhh  = (const float*)d_in[4];
    const float* Wout = (const float*)d_in[5];
    const float* bout = (const float*)d_in[6];

    float* hid = (float*)d_out;                  // hidden_states (B,T,H)
    float* out = hid + (size_t)M_TOTAL * HD;     // output_states (B,T,H)

    float* xproj;
    cudaGetSymbolAddress((void**)&xproj, g_xproj);

    gemm128_kernel<<<M_TOTAL / 64, 128>>>(seq, Wih, bih, bhh, xproj);
    rnn_rec_kernel<<<BQ, 128>>>(xproj, Whh, hid);
    gemm128_kernel<<<M_TOTAL / 64, 128>>>(hid, Wout, bout, nullptr, out);
}

// round 10
// speedup vs baseline: 2.1331x; 1.0581x over previous
#include <cuda_runtime.h>

#define BQ 64
#define TQ 2048
#define HD 128
#define M_TOTAL (BQ * TQ)
#define CHUNK 8          // xp rows staged per cp.async group
#define NTILE 2048       // 64-row tiles per GEMM
#define NWORK 200        // worker CTAs
#define GRID (BQ + NWORK)

// Scratch for x_proj, padded by 2 chunks so cp.async prefetch can run
// unconditionally past the end (allocation-free rule: __device__ globals).
__device__ float g_xproj[(size_t)M_TOTAL * HD + 2 * CHUNK * HD];
// g_flags[0..NTILE): xproj tile ready; [NTILE..2*NTILE): hidden tile ready
__device__ int g_flags[2 * NTILE];

// ---- packed fp32x2 helpers (sm_100+) ---------------------------------------
__device__ __forceinline__ void ffma2(unsigned long long& d,
                                      unsigned long long a,
                                      unsigned long long b) {
    asm("fma.rn.f32x2 %0, %1, %2, %0;" : "+l"(d) : "l"(a), "l"(b));
}
__device__ __forceinline__ unsigned long long addf2(unsigned long long a,
                                                    unsigned long long b) {
    unsigned long long d;
    asm("add.rn.f32x2 %0, %1, %2;" : "=l"(d) : "l"(a), "l"(b));
    return d;
}
__device__ __forceinline__ unsigned long long pack2(float lo, float hi) {
    unsigned long long p;
    asm("mov.b64 %0, {%1, %2};" : "=l"(p) : "r"(__float_as_uint(lo)), "r"(__float_as_uint(hi)));
    return p;
}
__device__ __forceinline__ void unpack2(unsigned long long p, float& lo, float& hi) {
    unsigned int a, b;
    asm("mov.b64 {%0, %1}, %2;" : "=r"(a), "=r"(b) : "l"(p));
    lo = __uint_as_float(a);
    hi = __uint_as_float(b);
}
__device__ __forceinline__ unsigned int smem_u32(const void* p) {
    unsigned int a;
    asm("{ .reg .u64 t; cvta.to.shared.u64 t, %1; cvt.u32.u64 %0, t; }" : "=r"(a) : "l"(p));
    return a;
}
__device__ __forceinline__ void cp_async16(unsigned int dst, const void* src) {
    asm volatile("cp.async.cg.shared.global [%0], [%1], 16;" :: "r"(dst), "l"(src));
}
__device__ __forceinline__ void cp_commit() {
    asm volatile("cp.async.commit_group;");
}
template <int N> __device__ __forceinline__ void cp_wait() {
    asm volatile("cp.async.wait_group %0;" :: "n"(N));
}

// ---- flag protocol ---------------------------------------------------------
__device__ __forceinline__ void wait_flag(int* f) {
    if (atomicAdd(f, 0) == 0) {
        int backoff = 64;
        do {
            __nanosleep(backoff);
            if (backoff < 2048) backoff <<= 1;
        } while (atomicAdd(f, 0) == 0);
    }
    __threadfence();   // acquire
}

// ---------------------------------------------------------------------------
// GEMM tile: C[m0..m0+64)[n] = sum_k A[m][k]*W[n][k] + bias (+bias2)
// 128 threads, 8m x 8n register tile, FFMA2. K split in 4 chunks of 32
// (24KB smem so >=2 CTAs/SM fit alongside the recurrence).
// pool layout: Wt = pool[0..4096)  [k][n] 32x128 ; At = pool[4096..6144) 32x64
// ---------------------------------------------------------------------------
__device__ __forceinline__ void gemm_tile(
    const float* __restrict__ A, const float* __restrict__ W,
    const float* __restrict__ bias, const float* __restrict__ bias2,
    float* __restrict__ C, int m0, float* pool)
{
    float* Wt = pool;
    float* At = pool + 32 * 128;
    const int tid = threadIdx.x;
    const int tx = tid & 15;
    const int ty = tid >> 4;

    unsigned long long acc2[8][4];
#pragma unroll
    for (int i = 0; i < 8; i++)
#pragma unroll
        for (int j = 0; j < 4; j++) acc2[i][j] = 0ull;

#pragma unroll
    for (int kc = 0; kc < 4; kc++) {
        // W staging: lanes cover consecutive n -> conflict-free STS
#pragma unroll
        for (int r = 0; r < 8; r++) {
            int i  = tid + r * 128;
            int n  = i & 127;
            int k0 = (i >> 7) << 2;
            float4 v = *(const float4*)(W + (size_t)n * 128 + kc * 32 + k0);
            Wt[(k0 + 0) * 128 + n] = v.x;
            Wt[(k0 + 1) * 128 + n] = v.y;
            Wt[(k0 + 2) * 128 + n] = v.z;
            Wt[(k0 + 3) * 128 + n] = v.w;
        }
        // A staging
#pragma unroll
        for (int r = 0; r < 4; r++) {
            int i  = tid + r * 128;
            int m  = i & 63;
            int k0 = (i >> 6) << 2;
            float4 v = *(const float4*)(A + (size_t)(m0 + m) * 128 + kc * 32 + k0);
            At[(k0 + 0) * 64 + m] = v.x;
            At[(k0 + 1) * 64 + m] = v.y;
            At[(k0 + 2) * 64 + m] = v.z;
            At[(k0 + 3) * 64 + m] = v.w;
        }
        __syncthreads();

#pragma unroll 8
        for (int k = 0; k < 32; k++) {
            float4 a0 = *(const float4*)(At + k * 64 + ty * 8);
            float4 a1 = *(const float4*)(At + k * 64 + ty * 8 + 4);
            ulonglong2 w0 = *(const ulonglong2*)(Wt + k * 128 + tx * 4);
            ulonglong2 w1 = *(const ulonglong2*)(Wt + k * 128 + 64 + tx * 4);
            float am[8] = {a0.x, a0.y, a0.z, a0.w, a1.x, a1.y, a1.z, a1.w};
#pragma unroll
            for (int i = 0; i < 8; i++) {
                unsigned long long ad = pack2(am[i], am[i]);
                ffma2(acc2[i][0], ad, w0.x);
                ffma2(acc2[i][1], ad, w0.y);
                ffma2(acc2[i][2], ad, w1.x);
                ffma2(acc2[i][3], ad, w1.y);
            }
        }
        __syncthreads();
    }

    float bb[8];
#pragma unroll
    for (int j = 0; j < 4; j++) {
        bb[j]     = bias[tx * 4 + j];
        bb[4 + j] = bias[64 + tx * 4 + j];
        if (bias2) {
            bb[j]     += bias2[tx * 4 + j];
            bb[4 + j] += bias2[64 + tx * 4 + j];
        }
    }
#pragma unroll
    for (int i = 0; i < 8; i++) {
        const int m = m0 + ty * 8 + i;
        float c[8];
#pragma unroll
        for (int j = 0; j < 4; j++) unpack2(acc2[i][j], c[2 * j], c[2 * j + 1]);
#pragma unroll
        for (int j = 0; j < 8; j++) c[j] += bb[j];
        float* crow = C + (size_t)m * 128;
        *(float4*)(crow + tx * 4)      = make_float4(c[0], c[1], c[2], c[3]);
        *(float4*)(crow + 64 + tx * 4) = make_float4(c[4], c[5], c[6], c[7]);
    }
}

// ---------------------------------------------------------------------------
// Fused persistent kernel.
//   CTAs [0,64):        recurrence (batch b = blockIdx.x), proven R9 inner loop
//   CTAs [64, 64+NWORK): GEMM workers: all GEMM1 tiles (tblk-major), then
//                        GEMM3 tiles gated on per-tile hidden flags.
// Tile index = tblk*64 + b  (b = tile&63, tblk = tile>>6, rows m0=b*TQ+tblk*64)
// ---------------------------------------------------------------------------
__global__ __launch_bounds__(128, 2) void fused_rnn_kernel(
    const float* __restrict__ seq,  const float* __restrict__ Wih,
    const float* __restrict__ bih,  const float* __restrict__ Whh,
    const float* __restrict__ bhh,  const float* __restrict__ Wout,
    const float* __restrict__ bout, float* __restrict__ xproj,
    float* __restrict__ hid,        float* __restrict__ out)
{
    __shared__ __align__(16) float pool[32 * 128 + 32 * 64];  // 24KB
    const int tid = threadIdx.x;

    if (blockIdx.x >= BQ) {
        // ------------------------- GEMM worker -------------------------
        const int wid = blockIdx.x - BQ;
        // Phase 1: xproj tiles (no waits -> guaranteed forward progress)
        for (int tile = wid; tile < NTILE; tile += NWORK) {
            const int bb = tile & 63, tblk = tile >> 6;
            gemm_tile(seq, Wih, bih, bhh, xproj, bb * TQ + tblk * 64, pool);
            __threadfence();
            __syncthreads();
            if (tid == 0) atomicExch(&g_flags[tile], 1);
        }
        // Phase 2: output tiles, gated on hidden flags
        for (int tile = wid; tile < NTILE; tile += NWORK) {
            if (tid == 0) wait_flag(&g_flags[NTILE + tile]);
            __syncthreads();
            const int bb = tile & 63, tblk = tile >> 6;
            gemm_tile(hid, Wout, bout, nullptr, out, bb * TQ + tblk * 64, pool);
        }
        return;
    }

    // --------------------------- recurrence ---------------------------
    const int b = blockIdx.x;
    float* sh_h  = pool;              // [2][HD]
    float* sh_xp = pool + 2 * HD;     // [2][CHUNK][HD]

    // full W_hh row j=tid in registers: 64 packed fp32x2
    unsigned long long w2[64];
    {
        const ulonglong2* wp = (const ulonglong2*)(Whh + (size_t)tid * 128);
#pragma unroll
        for (int i = 0; i < 32; i++) {
            ulonglong2 v = wp[i];
            w2[2 * i]     = v.x;
            w2[2 * i + 1] = v.y;
        }
    }

    sh_h[tid] = 0.f;

    const float* xp   = xproj + (size_t)b * TQ * HD;
    float*       hout = hid + (size_t)b * TQ * HD + tid;

    // cp.async staging: 4KB chunk / 128 threads = 32B (2x16B) per thread
    const int cp_row = tid >> 4;
    const int cp_col = (tid & 15) * 8;
    const unsigned int dst0 = smem_u32(sh_xp + (size_t)cp_row * HD + cp_col);
    const unsigned int dst1 = dst0 + CHUNK * HD * 4;
    const float* src_base = xp + (size_t)cp_row * HD + cp_col;

    // first xproj tile (tblk 0) must be ready before preloading chunks 0,1
    if (tid == 0) wait_flag(&g_flags[b]);
    __syncthreads();

    cp_async16(dst0,      src_base);
    cp_async16(dst0 + 16, src_base + 4);
    cp_commit();
    cp_async16(dst1,      src_base + CHUNK * HD);
    cp_async16(dst1 + 16, src_base + CHUNK * HD + 4);
    cp_commit();

    __syncthreads();  // sh_h init visible

#pragma unroll 1
    for (int tc = 0; tc < TQ / CHUNK; tc++) {
        cp_wait<1>();
        __syncthreads();

        const float* xrow = sh_xp + (size_t)(tc & 1) * CHUNK * HD + tid;

#pragma unroll 2
        for (int u = 0; u < CHUNK; u++) {
            const ulonglong2* hp = (const ulonglong2*)(sh_h + (u & 1) * HD);

            unsigned long long a2[4] = {0ull, 0ull, 0ull, 0ull};
#pragma unroll
            for (int i = 0; i < 32; i++) {
                ulonglong2 hv = hp[i];           // broadcast LDS
                ffma2(a2[i & 3], hv.x, w2[2 * i]);
                ffma2(a2[i & 3], hv.y, w2[2 * i + 1]);
            }
            unsigned long long p = addf2(addf2(a2[0], a2[1]), addf2(a2[2], a2[3]));
            float lo, hi;
            unpack2(p, lo, hi);

            const float x = lo + hi + xrow[(size_t)u * HD];
            const float e  = __expf(2.f * x);            // tanh = 1 - 2/(e^{2x}+1)
            const float hn = 1.f - __fdividef(2.f, e + 1.f);

            sh_h[((u + 1) & 1) * HD + tid] = hn;
            hout[(size_t)(tc * CHUNK + u) * HD] = hn;
            __syncthreads();
        }

        // publish hidden tile every 8 chunks (64 timesteps)
        if ((tc & 7) == 7) {
            __threadfence();
            __syncthreads();
            if (tid == 0) atomicExch(&g_flags[NTILE + (tc >> 3) * 64 + b], 1);
        }

        // refill just-consumed buffer with chunk tc+2; gate on producer flag
        {
            const int c2 = tc + 2;
            if ((c2 & 7) == 0 && c2 < TQ / CHUNK) {
                if (tid == 0) wait_flag(&g_flags[(c2 >> 3) * 64 + b]);
                __syncthreads();
            }
            const unsigned int d = (tc & 1) ? dst1 : dst0;
            const float* s = src_base + (size_t)c2 * CHUNK * HD;
            cp_async16(d,      s);
            cp_async16(d + 16, s + 4);
            cp_commit();
        }
    }
}

// ---------------------------------------------------------------------------
extern "C" void kernel_launch(void* const* d_in, const int* in_sizes, int n_in,
                              void* d_out, int out_size)
{
    const float* seq  = (const float*)d_in[0];
    const float* Wih  = (const float*)d_in[1];
    const float* bih  = (const float*)d_in[2];
    const float* Whh  = (const float*)d_in[3];
    const float* bhh  = (const float*)d_in[4];
    const float* Wout = (const float*)d_in[5];
    const float* bout = (const float*)d_in[6];

    float* hid = (float*)d_out;                  // hidden_states (B,T,H)
    float* out = hid + (size_t)M_TOTAL * HD;     // output_states (B,T,H)

    float* xproj;
    cudaGetSymbolAddress((void**)&xproj, g_xproj);
    void* flags;
    cudaGetSymbolAddress(&flags, g_flags);

    cudaMemsetAsync(flags, 0, 2 * NTILE * sizeof(int));
    fused_rnn_kernel<<<GRID, 128>>>(seq, Wih, bih, Whh, bhh, Wout, bout,
                                    xproj, hid, out);
}

// round 11
// speedup vs baseline: 2.5818x; 1.2103x over previous
#include <cuda_runtime.h>

#define BQ 64
#define TQ 2048
#define HD 128
#define M_TOTAL (BQ * TQ)
#define CHUNK 8          // xp rows staged per cp.async group
#define NTILE 2048       // 64-row tiles per GEMM
#define NWORK 84         // worker CTAs
#define GRID (BQ + NWORK) // 148 == SM count -> wave-1: every CTA solo on its SM

// Scratch for x_proj, padded by 2 chunks so cp.async prefetch can run
// unconditionally past the end (allocation-free rule: __device__ globals).
__device__ float g_xproj[(size_t)M_TOTAL * HD + 2 * CHUNK * HD];
// g_flags[0..NTILE): xproj tile ready; [NTILE..2*NTILE): hidden tile ready
__device__ int g_flags[2 * NTILE];

// ---- packed fp32x2 helpers (sm_100+) ---------------------------------------
__device__ __forceinline__ void ffma2(unsigned long long& d,
                                      unsigned long long a,
                                      unsigned long long b) {
    asm("fma.rn.f32x2 %0, %1, %2, %0;" : "+l"(d) : "l"(a), "l"(b));
}
__device__ __forceinline__ unsigned long long addf2(unsigned long long a,
                                                    unsigned long long b) {
    unsigned long long d;
    asm("add.rn.f32x2 %0, %1, %2;" : "=l"(d) : "l"(a), "l"(b));
    return d;
}
__device__ __forceinline__ unsigned long long pack2(float lo, float hi) {
    unsigned long long p;
    asm("mov.b64 %0, {%1, %2};" : "=l"(p) : "r"(__float_as_uint(lo)), "r"(__float_as_uint(hi)));
    return p;
}
__device__ __forceinline__ void unpack2(unsigned long long p, float& lo, float& hi) {
    unsigned int a, b;
    asm("mov.b64 {%0, %1}, %2;" : "=r"(a), "=r"(b) : "l"(p));
    lo = __uint_as_float(a);
    hi = __uint_as_float(b);
}
__device__ __forceinline__ unsigned int smem_u32(const void* p) {
    unsigned int a;
    asm("{ .reg .u64 t; cvta.to.shared.u64 t, %1; cvt.u32.u64 %0, t; }" : "=r"(a) : "l"(p));
    return a;
}
__device__ __forceinline__ void cp_async16(unsigned int dst, const void* src) {
    asm volatile("cp.async.cg.shared.global [%0], [%1], 16;" :: "r"(dst), "l"(src));
}
__device__ __forceinline__ void cp_commit() {
    asm volatile("cp.async.commit_group;");
}
template <int N> __device__ __forceinline__ void cp_wait() {
    asm volatile("cp.async.wait_group %0;" :: "n"(N));
}

// ---- flag protocol ---------------------------------------------------------
__device__ __forceinline__ void wait_flag(int* f) {
    if (atomicAdd(f, 0) == 0) {
        int backoff = 64;
        do {
            __nanosleep(backoff);
            if (backoff < 2048) backoff <<= 1;
        } while (atomicAdd(f, 0) == 0);
    }
    __threadfence();   // acquire
}

// ---------------------------------------------------------------------------
// GEMM tile: C[m0..m0+64)[n] = sum_k A[m][k]*W[n][k] + bias (+bias2)
// 128 threads, 8m x 8n register tile, FFMA2, K in two 64-chunks (R5-proven).
// pool layout: Wt = pool[0..8192) [k][n] 64x128 ; At = pool[8192..12288) 64x64
// ---------------------------------------------------------------------------
__device__ __forceinline__ void gemm_tile(
    const float* __restrict__ A, const float* __restrict__ W,
    const float* __restrict__ bias, const float* __restrict__ bias2,
    float* __restrict__ C, int m0, float* pool)
{
    float* Wt = pool;
    float* At = pool + 64 * 128;
    const int tid = threadIdx.x;
    const int tx = tid & 15;
    const int ty = tid >> 4;

    unsigned long long acc2[8][4];
#pragma unroll
    for (int i = 0; i < 8; i++)
#pragma unroll
        for (int j = 0; j < 4; j++) acc2[i][j] = 0ull;

#pragma unroll
    for (int kc = 0; kc < 2; kc++) {
        // W staging: lanes cover consecutive n -> conflict-free STS
#pragma unroll
        for (int r = 0; r < 16; r++) {
            int i  = tid + r * 128;
            int n  = i & 127;
            int k0 = (i >> 7) << 2;
            float4 v = *(const float4*)(W + (size_t)n * 128 + kc * 64 + k0);
            Wt[(k0 + 0) * 128 + n] = v.x;
            Wt[(k0 + 1) * 128 + n] = v.y;
            Wt[(k0 + 2) * 128 + n] = v.z;
            Wt[(k0 + 3) * 128 + n] = v.w;
        }
        // A staging
#pragma unroll
        for (int r = 0; r < 8; r++) {
            int i  = tid + r * 128;
            int m  = i & 63;
            int k0 = (i >> 6) << 2;
            float4 v = *(const float4*)(A + (size_t)(m0 + m) * 128 + kc * 64 + k0);
            At[(k0 + 0) * 64 + m] = v.x;
            At[(k0 + 1) * 64 + m] = v.y;
            At[(k0 + 2) * 64 + m] = v.z;
            At[(k0 + 3) * 64 + m] = v.w;
        }
        __syncthreads();

#pragma unroll 8
        for (int k = 0; k < 64; k++) {
            float4 a0 = *(const float4*)(At + k * 64 + ty * 8);
            float4 a1 = *(const float4*)(At + k * 64 + ty * 8 + 4);
            ulonglong2 w0 = *(const ulonglong2*)(Wt + k * 128 + tx * 4);
            ulonglong2 w1 = *(const ulonglong2*)(Wt + k * 128 + 64 + tx * 4);
            float am[8] = {a0.x, a0.y, a0.z, a0.w, a1.x, a1.y, a1.z, a1.w};
#pragma unroll
            for (int i = 0; i < 8; i++) {
                unsigned long long ad = pack2(am[i], am[i]);
                ffma2(acc2[i][0], ad, w0.x);
                ffma2(acc2[i][1], ad, w0.y);
                ffma2(acc2[i][2], ad, w1.x);
                ffma2(acc2[i][3], ad, w1.y);
            }
        }
        __syncthreads();
    }

    float bb[8];
#pragma unroll
    for (int j = 0; j < 4; j++) {
        bb[j]     = bias[tx * 4 + j];
        bb[4 + j] = bias[64 + tx * 4 + j];
        if (bias2) {
            bb[j]     += bias2[tx * 4 + j];
            bb[4 + j] += bias2[64 + tx * 4 + j];
        }
    }
#pragma unroll
    for (int i = 0; i < 8; i++) {
        const int m = m0 + ty * 8 + i;
        float c[8];
#pragma unroll
        for (int j = 0; j < 4; j++) unpack2(acc2[i][j], c[2 * j], c[2 * j + 1]);
#pragma unroll
        for (int j = 0; j < 8; j++) c[j] += bb[j];
        float* crow = C + (size_t)m * 128;
        *(float4*)(crow + tx * 4)      = make_float4(c[0], c[1], c[2], c[3]);
        *(float4*)(crow + 64 + tx * 4) = make_float4(c[4], c[5], c[6], c[7]);
    }
}

// ---------------------------------------------------------------------------
// Fused persistent kernel, GRID=148 (1 CTA per SM -> zero co-residency).
//   CTAs [0,64):      recurrence (batch b = blockIdx.x), proven R9 inner loop
//   CTAs [64,148):    GEMM workers: all GEMM1 tiles (tblk-major), then GEMM3
//                     tiles gated on per-tile hidden flags.
// Tile index = tblk*64 + b  (b = tile&63, tblk = tile>>6, rows m0=b*TQ+tblk*64)
// ---------------------------------------------------------------------------
__global__ __launch_bounds__(128, 1) void fused_rnn_kernel(
    const float* __restrict__ seq,  const float* __restrict__ Wih,
    const float* __restrict__ bih,  const float* __restrict__ Whh,
    const float* __restrict__ bhh,  const float* __restrict__ Wout,
    const float* __restrict__ bout, float* __restrict__ xproj,
    float* __restrict__ hid,        float* __restrict__ out)
{
    __shared__ __align__(16) float pool[64 * 128 + 64 * 64];  // 48KB
    const int tid = threadIdx.x;

    if (blockIdx.x >= BQ) {
        // ------------------------- GEMM worker -------------------------
        const int wid = blockIdx.x - BQ;
        // Phase 1: xproj tiles, tblk-major (no waits -> forward progress)
        for (int tile = wid; tile < NTILE; tile += NWORK) {
            const int bb = tile & 63, tblk = tile >> 6;
            gemm_tile(seq, Wih, bih, bhh, xproj, bb * TQ + tblk * 64, pool);
            __threadfence();
            __syncthreads();
            if (tid == 0) atomicExch(&g_flags[tile], 1);
        }
        // Phase 2: output tiles, gated on hidden flags
        for (int tile = wid; tile < NTILE; tile += NWORK) {
            if (tid == 0) wait_flag(&g_flags[NTILE + tile]);
            __syncthreads();
            const int bb = tile & 63, tblk = tile >> 6;
            gemm_tile(hid, Wout, bout, nullptr, out, bb * TQ + tblk * 64, pool);
        }
        return;
    }

    // --------------------------- recurrence ---------------------------
    const int b = blockIdx.x;
    float* sh_h  = pool;              // [2][HD]
    float* sh_xp = pool + 2 * HD;     // [2][CHUNK][HD]

    // full W_hh row j=tid in registers: 64 packed fp32x2
    unsigned long long w2[64];
    {
        const ulonglong2* wp = (const ulonglong2*)(Whh + (size_t)tid * 128);
#pragma unroll
        for (int i = 0; i < 32; i++) {
            ulonglong2 v = wp[i];
            w2[2 * i]     = v.x;
            w2[2 * i + 1] = v.y;
        }
    }

    sh_h[tid] = 0.f;

    const float* xp   = xproj + (size_t)b * TQ * HD;
    float*       hout = hid + (size_t)b * TQ * HD + tid;

    // cp.async staging: 4KB chunk / 128 threads = 32B (2x16B) per thread
    const int cp_row = tid >> 4;
    const int cp_col = (tid & 15) * 8;
    const unsigned int dst0 = smem_u32(sh_xp + (size_t)cp_row * HD + cp_col);
    const unsigned int dst1 = dst0 + CHUNK * HD * 4;
    const float* src_base = xp + (size_t)cp_row * HD + cp_col;

    // first xproj tile (tblk 0) must be ready before preloading chunks 0,1
    if (tid == 0) wait_flag(&g_flags[b]);
    __syncthreads();

    cp_async16(dst0,      src_base);
    cp_async16(dst0 + 16, src_base + 4);
    cp_commit();
    cp_async16(dst1,      src_base + CHUNK * HD);
    cp_async16(dst1 + 16, src_base + CHUNK * HD + 4);
    cp_commit();

    __syncthreads();  // sh_h init visible

#pragma unroll 1
    for (int tc = 0; tc < TQ / CHUNK; tc++) {
        cp_wait<1>();
        __syncthreads();

        const float* xrow = sh_xp + (size_t)(tc & 1) * CHUNK * HD + tid;

#pragma unroll 2
        for (int u = 0; u < CHUNK; u++) {
            const ulonglong2* hp = (const ulonglong2*)(sh_h + (u & 1) * HD);

            unsigned long long a2[4] = {0ull, 0ull, 0ull, 0ull};
#pragma unroll
            for (int i = 0; i < 32; i++) {
                ulonglong2 hv = hp[i];           // broadcast LDS
                ffma2(a2[i & 3], hv.x, w2[2 * i]);
                ffma2(a2[i & 3], hv.y, w2[2 * i + 1]);
            }
            unsigned long long p = addf2(addf2(a2[0], a2[1]), addf2(a2[2], a2[3]));
            float lo, hi;
            unpack2(p, lo, hi);

            const float x = lo + hi + xrow[(size_t)u * HD];
            const float e  = __expf(2.f * x);            // tanh = 1 - 2/(e^{2x}+1)
            const float hn = 1.f - __fdividef(2.f, e + 1.f);

            sh_h[((u + 1) & 1) * HD + tid] = hn;
            hout[(size_t)(tc * CHUNK + u) * HD] = hn;
            __syncthreads();
        }

        // publish hidden tile every 8 chunks (64 timesteps)
        if ((tc & 7) == 7) {
            __threadfence();
            __syncthreads();
            if (tid == 0) atomicExch(&g_flags[NTILE + (tc >> 3) * 64 + b], 1);
        }

        // refill just-consumed buffer with chunk tc+2; gate on producer flag
        {
            const int c2 = tc + 2;
            if ((c2 & 7) == 0 && c2 < TQ / CHUNK) {
                if (tid == 0) wait_flag(&g_flags[(c2 >> 3) * 64 + b]);
                __syncthreads();
            }
            const unsigned int d = (tc & 1) ? dst1 : dst0;
            const float* s = src_base + (size_t)c2 * CHUNK * HD;
            cp_async16(d,      s);
            cp_async16(d + 16, s + 4);
            cp_commit();
        }
    }
}

// ---------------------------------------------------------------------------
extern "C" void kernel_launch(void* const* d_in, const int* in_sizes, int n_in,
                              void* d_out, int out_size)
{
    const float* seq  = (const float*)d_in[0];
    const float* Wih  = (const float*)d_in[1];
    const float* bih  = (const float*)d_in[2];
    const float* Whh  = (const float*)d_in[3];
    const float* bhh  = (const float*)d_in[4];
    const float* Wout = (const float*)d_in[5];
    const float* bout = (const float*)d_in[6];

    float* hid = (float*)d_out;                  // hidden_states (B,T,H)
    float* out = hid + (size_t)M_TOTAL * HD;     // output_states (B,T,H)

    float* xproj;
    cudaGetSymbolAddress((void**)&xproj, g_xproj);
    void* flags;
    cudaGetSymbolAddress(&flags, g_flags);

    cudaMemsetAsync(flags, 0, 2 * NTILE * sizeof(int));
    fused_rnn_kernel<<<GRID, 128>>>(seq, Wih, bih, Whh, bhh, Wout, bout,
                                    xproj, hid, out);
}